// round 10
// baseline (speedup 1.0000x reference)
#include <cuda_runtime.h>

#define BB 16
#define LL 192
#define EE 128
#define TT 25
#define NI (LL - TT - 1)            // 166
#define OUT_L (TT + 1 + NI * LL)    // 31898
#define E4 (EE / 4)                 // 32 float4 per row
#define TPB 256
#define WARPS (TPB / 32)            // 8
#define L_RANGE 16                  // l-rows per CTA
#define LSPLITS (LL / L_RANGE)      // 12
#define NPASS (L_RANGE / WARPS)     // 2  -> 8 s-regs/thread
#define I_PER_BLK 12
#define ICH ((NI + I_PER_BLK - 1) / I_PER_BLK)  // 14  (R5 optimum)

// sigmoid(z) = 0.5*tanh(z/2) + 0.5  -> single MUFU op (tanh.approx.f32)
__device__ __forceinline__ float fast_sigmoid_half(float zhalf) {
    float t;
    asm("tanh.approx.f32 %0, %1;" : "=f"(t) : "f"(zhalf));
    return fmaf(0.5f, t, 0.5f);
}

// ---------------------------------------------------------------------------
// Single fused kernel: blocks[b,i,l,e] = xp + s0[b,l,e]*(xi-xp)
//   s0 = sigmoid(x*(W0-W1) + (b0-b1))  (2-way softmax collapsed; s1 = 1-s0)
//   xi = x[b, i+T+1, e], xp = x[b, i+1, e]
// Per-CTA sigmoid prologue: tanh.approx, 1 MUFU/elem, ~1.1us chip-wide.
// This round: no software prefetch (saves 8 regs) + launch_bounds(256,8)
// -> target 64 warps/SM; warp parallelism replaces the 2-stage pipeline.
// Grid (14,12,16) = 2688 CTAs, pointer-increment addressing,
// warp-coalesced 512B streaming STG.128 rows.
// ---------------------------------------------------------------------------
__global__ void __launch_bounds__(TPB, 8)
fused_kernel(const float* __restrict__ x,
             const float* __restrict__ W,
             const float* __restrict__ bv,
             float* __restrict__ out) {
    const int b  = blockIdx.z;
    const int l0 = blockIdx.y * L_RANGE;
    const int e4 = threadIdx.x & (E4 - 1);     // 0..31, contiguous in warp
    const int w  = threadIdx.x >> 5;           // 0..7, constant in warp

    const float4* xb = reinterpret_cast<const float4*>(x) + b * (LL * E4);
    float4* o4 = reinterpret_cast<float4*>(out);

    // Head copy: out[b, 0:26, :] = x[b, 0:26, :] (one CTA per batch)
    if (blockIdx.x == 0 && blockIdx.y == 0) {
        const size_t ob = (size_t)b * (OUT_L * E4);
        #pragma unroll
        for (int k = threadIdx.x; k < (TT + 1) * E4; k += TPB)
            __stcs(o4 + ob + k, xb[k]);
    }

    // Inline sigmoid for this thread's 2 s-float4 (i-invariant within CTA).
    // Fold the /2 of tanh-sigmoid into the affine: zhalf = x*dW2 + db2.
    const float dW2 = 0.5f * (W[0] - W[1]);
    const float db2 = 0.5f * (bv[0] - bv[1]);
    float4 s[NPASS];
    #pragma unroll
    for (int p = 0; p < NPASS; p++) {
        float4 xv = xb[(l0 + w + p * WARPS) * E4 + e4];
        s[p].x = fast_sigmoid_half(fmaf(xv.x, dW2, db2));
        s[p].y = fast_sigmoid_half(fmaf(xv.y, dW2, db2));
        s[p].z = fast_sigmoid_half(fmaf(xv.z, dW2, db2));
        s[p].w = fast_sigmoid_half(fmaf(xv.w, dW2, db2));
    }

    const int i0 = blockIdx.x * I_PER_BLK;
    const int iend = min(i0 + I_PER_BLK, NI);
    if (i0 >= iend) return;
    const int n_iter = iend - i0;

    // Hot-loop pointers: advance by constants per i (no per-i multiplies)
    const float4* pxi = xb + (i0 + TT + 1) * E4 + e4;
    const float4* pxp = xb + (i0 + 1) * E4 + e4;
    float4* po = o4 + ((size_t)b * OUT_L + (TT + 1) + (size_t)i0 * LL + l0 + w) * E4 + e4;

    for (int it = 0; it < n_iter; it++) {
        float4 xi = *pxi;
        float4 xp = *pxp;
        pxi += E4; pxp += E4;

        float4 d;
        d.x = xi.x - xp.x; d.y = xi.y - xp.y;
        d.z = xi.z - xp.z; d.w = xi.w - xp.w;

        #pragma unroll
        for (int p = 0; p < NPASS; p++) {
            float4 o;
            o.x = fmaf(s[p].x, d.x, xp.x);
            o.y = fmaf(s[p].y, d.y, xp.y);
            o.z = fmaf(s[p].z, d.z, xp.z);
            o.w = fmaf(s[p].w, d.w, xp.w);
            // write-once output: streaming store, evict-first in L2
            __stcs(po + p * (WARPS * E4), o);
        }
        po += (size_t)(LL * E4);   // next i: advance one L-block
    }
}

// ---------------------------------------------------------------------------
extern "C" void kernel_launch(void* const* d_in, const int* in_sizes, int n_in,
                              void* d_out, int out_size) {
    const float* x  = (const float*)d_in[0];  // (16,192,128) f32
    const float* W  = (const float*)d_in[1];  // (2,1) f32
    const float* bv = (const float*)d_in[2];  // (2,) f32
    float* out = (float*)d_out;               // (16,31898,128) f32

    dim3 grid(ICH, LSPLITS, BB);   // 14 x 12 x 16 = 2688 CTAs
    fused_kernel<<<grid, TPB>>>(x, W, bv, out);
}

// round 11
// speedup vs baseline: 1.1062x; 1.1062x over previous
#include <cuda_runtime.h>

#define BB 16
#define LL 192
#define EE 128
#define TT 25
#define NI (LL - TT - 1)            // 166
#define OUT_L (TT + 1 + NI * LL)    // 31898
#define E4 (EE / 4)                 // 32 float4 per row
#define TPB 256
#define WARPS (TPB / 32)            // 8
#define L_RANGE 16                  // l-rows per CTA
#define LSPLITS (LL / L_RANGE)      // 12
#define NPASS (L_RANGE / WARPS)     // 2  -> 8 s-regs/thread
#define I_PER_BLK 12
#define ICH ((NI + I_PER_BLK - 1) / I_PER_BLK)  // 14  (empirical optimum)

// sigmoid(z) = 0.5*tanh(z/2) + 0.5  -> single MUFU op (tanh.approx.f32)
__device__ __forceinline__ float fast_sigmoid_half(float zhalf) {
    float t;
    asm("tanh.approx.f32 %0, %1;" : "=f"(t) : "f"(zhalf));
    return fmaf(0.5f, t, 0.5f);
}

// ---------------------------------------------------------------------------
// Single fused kernel (R9 configuration — empirical optimum):
//   blocks[b,i,l,e] = xp + s0[b,l,e]*(xi-xp)
//   s0 = sigmoid(x*(W0-W1) + (b0-b1)); xi = x[b,i+T+1,e], xp = x[b,i+1,e]
// Proven levers kept: tanh.approx sigmoid prologue (~1.1us chip-wide),
// grid (14,12,16)=2688 CTAs, launch_bounds(256,6) -> ~44 warps/SM (the
// bandwidth-vs-occupancy knee), 2-STAGE xi/xp PREFETCH (load-bearing: its
// removal at 96% occ cost +8us in R10), pointer-increment addressing,
// warp-coalesced 512B streaming STG.128 rows.
// This round: all-32-bit index math (total out = 16.3M float4 < 2^31).
// ---------------------------------------------------------------------------
__global__ void __launch_bounds__(TPB, 6)
fused_kernel(const float* __restrict__ x,
             const float* __restrict__ W,
             const float* __restrict__ bv,
             float* __restrict__ out) {
    const int b  = blockIdx.z;
    const int l0 = blockIdx.y * L_RANGE;
    const int e4 = threadIdx.x & (E4 - 1);     // 0..31, contiguous in warp
    const int w  = threadIdx.x >> 5;           // 0..7, constant in warp

    const float4* xb = reinterpret_cast<const float4*>(x) + b * (LL * E4);
    float4* o4 = reinterpret_cast<float4*>(out);

    // Head copy: out[b, 0:26, :] = x[b, 0:26, :] (one CTA per batch)
    if (blockIdx.x == 0 && blockIdx.y == 0) {
        const unsigned ob = (unsigned)b * (OUT_L * E4);
        #pragma unroll
        for (int k = threadIdx.x; k < (TT + 1) * E4; k += TPB)
            __stcs(o4 + ob + k, xb[k]);
    }

    // Inline sigmoid for this thread's 2 s-float4 (i-invariant within CTA).
    // Fold the /2 of tanh-sigmoid into the affine: zhalf = x*dW2 + db2.
    const float dW2 = 0.5f * (W[0] - W[1]);
    const float db2 = 0.5f * (bv[0] - bv[1]);
    float4 s[NPASS];
    #pragma unroll
    for (int p = 0; p < NPASS; p++) {
        float4 xv = xb[(l0 + w + p * WARPS) * E4 + e4];
        s[p].x = fast_sigmoid_half(fmaf(xv.x, dW2, db2));
        s[p].y = fast_sigmoid_half(fmaf(xv.y, dW2, db2));
        s[p].z = fast_sigmoid_half(fmaf(xv.z, dW2, db2));
        s[p].w = fast_sigmoid_half(fmaf(xv.w, dW2, db2));
    }

    const int i0 = blockIdx.x * I_PER_BLK;
    const int iend = min(i0 + I_PER_BLK, NI);
    if (i0 >= iend) return;
    const int n_iter = iend - i0;

    // Hot-loop pointers: advance by constants per i (no per-i multiplies).
    // 32-bit offsets: max out index = 16*31898*32 = 16.3M < 2^31.
    const float4* pxi = xb + (i0 + TT + 1) * E4 + e4;
    const float4* pxp = xb + (i0 + 1) * E4 + e4;
    float4* po = o4 + ((unsigned)b * (OUT_L * E4)
                       + (unsigned)((TT + 1) + i0 * LL + l0 + w) * E4 + e4);

    // 2-stage pipeline on xi/xp (load-bearing — do not remove)
    float4 xi = *pxi;
    float4 xp = *pxp;

    for (int it = 0; it < n_iter; it++) {
        float4 nxi, nxp;
        if (it + 1 < n_iter) {
            nxi = pxi[E4];
            nxp = pxp[E4];
        }
        pxi += E4; pxp += E4;

        float4 d;
        d.x = xi.x - xp.x; d.y = xi.y - xp.y;
        d.z = xi.z - xp.z; d.w = xi.w - xp.w;

        #pragma unroll
        for (int p = 0; p < NPASS; p++) {
            float4 o;
            o.x = fmaf(s[p].x, d.x, xp.x);
            o.y = fmaf(s[p].y, d.y, xp.y);
            o.z = fmaf(s[p].z, d.z, xp.z);
            o.w = fmaf(s[p].w, d.w, xp.w);
            // write-once output: streaming store, evict-first in L2
            __stcs(po + p * (WARPS * E4), o);
        }
        po += (LL * E4);   // next i: advance one L-block

        xi = nxi; xp = nxp;
    }
}

// ---------------------------------------------------------------------------
extern "C" void kernel_launch(void* const* d_in, const int* in_sizes, int n_in,
                              void* d_out, int out_size) {
    const float* x  = (const float*)d_in[0];  // (16,192,128) f32
    const float* W  = (const float*)d_in[1];  // (2,1) f32
    const float* bv = (const float*)d_in[2];  // (2,) f32
    float* out = (float*)d_out;               // (16,31898,128) f32

    dim3 grid(ICH, LSPLITS, BB);   // 14 x 12 x 16 = 2688 CTAs
    fused_kernel<<<grid, TPB>>>(x, W, bv, out);
}

// round 12
// speedup vs baseline: 1.1078x; 1.0015x over previous
#include <cuda_runtime.h>

#define BB 16
#define LL 192
#define EE 128
#define TT 25
#define NI (LL - TT - 1)            // 166
#define OUT_L (TT + 1 + NI * LL)    // 31898
#define E4 (EE / 4)                 // 32 float4 per row
#define TPB 256
#define WARPS (TPB / 32)            // 8
#define L_RANGE 16                  // l-rows per CTA
#define LSPLITS (LL / L_RANGE)      // 12
#define NPASS (L_RANGE / WARPS)     // 2  -> 8 s-regs/thread
#define I_PER_BLK 12
#define ICH ((NI + I_PER_BLK - 1) / I_PER_BLK)  // 14  (empirical optimum)
#define HEAD4 ((TT + 1) * E4)       // 832 float4 of head rows per batch
#define HEAD_PER_Y ((HEAD4 + LSPLITS - 1) / LSPLITS)  // 70

// sigmoid(z) = 0.5*tanh(z/2) + 0.5  -> single MUFU op (tanh.approx.f32)
__device__ __forceinline__ float fast_sigmoid_half(float zhalf) {
    float t;
    asm("tanh.approx.f32 %0, %1;" : "=f"(t) : "f"(zhalf));
    return fmaf(0.5f, t, 0.5f);
}

// ---------------------------------------------------------------------------
// Single fused kernel (R9 configuration + balanced head copy):
//   blocks[b,i,l,e] = xp + s0[b,l,e]*(xi-xp)
//   s0 = sigmoid(x*(W0-W1) + (b0-b1)); xi = x[b,i+T+1,e], xp = x[b,i+1,e]
// Proven levers: tanh.approx sigmoid prologue, grid (14,12,16)=2688 CTAs,
// launch_bounds(256,6) = occupancy knee, 2-stage xi/xp prefetch
// (load-bearing), pointer-increment addressing, streaming STG.128 rows.
// New: head copy spread over all 12 y-CTAs per batch (70 f4 each instead of
// 832 on one CTA) -> removes the +14% straggler CTAs from the first wave.
// ---------------------------------------------------------------------------
__global__ void __launch_bounds__(TPB, 6)
fused_kernel(const float* __restrict__ x,
             const float* __restrict__ W,
             const float* __restrict__ bv,
             float* __restrict__ out) {
    const int b  = blockIdx.z;
    const int l0 = blockIdx.y * L_RANGE;
    const int e4 = threadIdx.x & (E4 - 1);     // 0..31, contiguous in warp
    const int w  = threadIdx.x >> 5;           // 0..7, constant in warp

    const float4* xb = reinterpret_cast<const float4*>(x) + b * (LL * E4);
    float4* o4 = reinterpret_cast<float4*>(out);

    // Head copy: out[b, 0:26, :] = x[b, 0:26, :], split across the 12 y-CTAs
    if (blockIdx.x == 0) {
        const unsigned ob = (unsigned)b * (OUT_L * E4);
        const int k0 = blockIdx.y * HEAD_PER_Y;
        const int k1 = min(k0 + HEAD_PER_Y, HEAD4);
        for (int k = k0 + (int)threadIdx.x; k < k1; k += TPB)
            __stcs(o4 + ob + k, xb[k]);
    }

    // Inline sigmoid for this thread's 2 s-float4 (i-invariant within CTA).
    // Fold the /2 of tanh-sigmoid into the affine: zhalf = x*dW2 + db2.
    const float dW2 = 0.5f * (W[0] - W[1]);
    const float db2 = 0.5f * (bv[0] - bv[1]);
    float4 s[NPASS];
    #pragma unroll
    for (int p = 0; p < NPASS; p++) {
        float4 xv = xb[(l0 + w + p * WARPS) * E4 + e4];
        s[p].x = fast_sigmoid_half(fmaf(xv.x, dW2, db2));
        s[p].y = fast_sigmoid_half(fmaf(xv.y, dW2, db2));
        s[p].z = fast_sigmoid_half(fmaf(xv.z, dW2, db2));
        s[p].w = fast_sigmoid_half(fmaf(xv.w, dW2, db2));
    }

    const int i0 = blockIdx.x * I_PER_BLK;
    const int iend = min(i0 + I_PER_BLK, NI);
    if (i0 >= iend) return;
    const int n_iter = iend - i0;

    // Hot-loop pointers: advance by constants per i (no per-i multiplies).
    // 32-bit offsets: max out index = 16*31898*32 = 16.3M < 2^31.
    const float4* pxi = xb + (i0 + TT + 1) * E4 + e4;
    const float4* pxp = xb + (i0 + 1) * E4 + e4;
    float4* po = o4 + ((unsigned)b * (OUT_L * E4)
                       + (unsigned)((TT + 1) + i0 * LL + l0 + w) * E4 + e4);

    // 2-stage pipeline on xi/xp (load-bearing — do not remove)
    float4 xi = *pxi;
    float4 xp = *pxp;

    for (int it = 0; it < n_iter; it++) {
        float4 nxi, nxp;
        if (it + 1 < n_iter) {
            nxi = pxi[E4];
            nxp = pxp[E4];
        }
        pxi += E4; pxp += E4;

        float4 d;
        d.x = xi.x - xp.x; d.y = xi.y - xp.y;
        d.z = xi.z - xp.z; d.w = xi.w - xp.w;

        #pragma unroll
        for (int p = 0; p < NPASS; p++) {
            float4 o;
            o.x = fmaf(s[p].x, d.x, xp.x);
            o.y = fmaf(s[p].y, d.y, xp.y);
            o.z = fmaf(s[p].z, d.z, xp.z);
            o.w = fmaf(s[p].w, d.w, xp.w);
            // write-once output: streaming store, evict-first in L2
            __stcs(po + p * (WARPS * E4), o);
        }
        po += (LL * E4);   // next i: advance one L-block

        xi = nxi; xp = nxp;
    }
}

// ---------------------------------------------------------------------------
extern "C" void kernel_launch(void* const* d_in, const int* in_sizes, int n_in,
                              void* d_out, int out_size) {
    const float* x  = (const float*)d_in[0];  // (16,192,128) f32
    const float* W  = (const float*)d_in[1];  // (2,1) f32
    const float* bv = (const float*)d_in[2];  // (2,) f32
    float* out = (float*)d_out;               // (16,31898,128) f32

    dim3 grid(ICH, LSPLITS, BB);   // 14 x 12 x 16 = 2688 CTAs
    fused_kernel<<<grid, TPB>>>(x, W, bv, out);
}